// round 15
// baseline (speedup 1.0000x reference)
#include <cuda_runtime.h>
#include <cuda_fp16.h>
#include <stdint.h>
#include <math.h>

// ---------------------------------------------------------------------------
// Problem constants
// ---------------------------------------------------------------------------
#define VOCABN 32000
#define BATCH  128
#define BTN    256          // 2*BATCH
#define NTREEN 1023
#define NPRE   1280         // iou(768) | f0(256) | f1(256)

// ---------------------------------------------------------------------------
// Scratch (device globals)
// ---------------------------------------------------------------------------
__device__ __align__(16) __half g_emb  [(size_t)VOCABN * 256];
__device__ __align__(16) __half g_Wt   [768 * 256];
__device__ __align__(16) __half g_Wc   [NPRE * 256];
__device__ __align__(16) __half g_table[(size_t)VOCABN * 768];
__device__ __align__(16) __half g_hleaf[(size_t)VOCABN * 256];   // leaf h per vocab (16MB, L2)
__device__ __align__(16) float  g_cleaf[(size_t)VOCABN * 256];   // leaf c per vocab (33MB, fp32)
__device__ __align__(16) __half g_h    [(size_t)BTN * NTREEN * 256];  // internal nodes only
__device__ __align__(16) __half g_c16  [(size_t)BTN * NTREEN * 256];  // internal c, fp16
__device__ __align__(16) __half g_hsum [(size_t)65536 * 256];
__device__ __align__(16) __half g_pre  [(size_t)65536 * NPRE];

// ---------------------------------------------------------------------------
// Helpers
// ---------------------------------------------------------------------------
__device__ __forceinline__ float sigf(float x)   { return 1.0f / (1.0f + __expf(-x)); }
__device__ __forceinline__ float tanhf_(float x) { return 2.0f / (1.0f + __expf(-2.0f * x)) - 1.0f; }

__device__ __forceinline__ uint32_t smem_u32(const void* p) {
    uint32_t a;
    asm("{ .reg .u64 t; cvta.to.shared.u64 t, %1; cvt.u32.u64 %0, t; }" : "=r"(a) : "l"(p));
    return a;
}
__device__ __forceinline__ float4 ldh4(const __half2* p) {
    __half2 a = p[0], b = p[1];
    return make_float4(__low2float(a), __high2float(a),
                       __low2float(b), __high2float(b));
}
__device__ __forceinline__ float4 unp_h4(uint2 u) {
    return make_float4(
        __half2float(__ushort_as_half((unsigned short)(u.x & 0xFFFF))),
        __half2float(__ushort_as_half((unsigned short)(u.x >> 16))),
        __half2float(__ushort_as_half((unsigned short)(u.y & 0xFFFF))),
        __half2float(__ushort_as_half((unsigned short)(u.y >> 16))));
}
__device__ __forceinline__ uint2 pack_h4(const float h[4]) {
    unsigned short b[4];
    #pragma unroll
    for (int e = 0; e < 4; e++) b[e] = __half_as_ushort(__float2half_rn(h[e]));
    return make_uint2(b[0] | ((unsigned)b[1] << 16), b[2] | ((unsigned)b[3] << 16));
}

// ---------------------------------------------------------------------------
// Baseline-PTX tensor ops + cp.async
// ---------------------------------------------------------------------------
__device__ __forceinline__ void ldm_x4(uint32_t r[4], uint32_t addr) {
    asm volatile("ldmatrix.sync.aligned.m8n8.x4.shared.b16 {%0,%1,%2,%3}, [%4];"
        : "=r"(r[0]), "=r"(r[1]), "=r"(r[2]), "=r"(r[3]) : "r"(addr));
}
__device__ __forceinline__ void ldm_x2(uint32_t r[2], uint32_t addr) {
    asm volatile("ldmatrix.sync.aligned.m8n8.x2.shared.b16 {%0,%1}, [%2];"
        : "=r"(r[0]), "=r"(r[1]) : "r"(addr));
}
__device__ __forceinline__ void mma_f16(float c[4], const uint32_t a[4], const uint32_t b[2]) {
    asm volatile("mma.sync.aligned.m16n8k16.row.col.f32.f16.f16.f32 "
        "{%0,%1,%2,%3}, {%4,%5,%6,%7}, {%8,%9}, {%0,%1,%2,%3};"
        : "+f"(c[0]), "+f"(c[1]), "+f"(c[2]), "+f"(c[3])
        : "r"(a[0]), "r"(a[1]), "r"(a[2]), "r"(a[3]), "r"(b[0]), "r"(b[1]));
}
#define CP16(dst, src) asm volatile("cp.async.cg.shared.global [%0], [%1], 16;" :: "r"(dst), "l"(src))
#define CP_COMMIT()    asm volatile("cp.async.commit_group;" ::: "memory")
#define CP_WAIT1()     asm volatile("cp.async.wait_group 1;" ::: "memory")
#define CP_WAIT0()     asm volatile("cp.async.wait_group 0;" ::: "memory")

// ---------------------------------------------------------------------------
// Prep kernels
// ---------------------------------------------------------------------------
__global__ __launch_bounds__(256) void emb_f16(const float* __restrict__ src)
{
    const int idx = blockIdx.x * 256 + threadIdx.x;
    g_emb[idx] = __float2half_rn(src[idx]);
}
__global__ __launch_bounds__(256) void wt_f16(const float* __restrict__ src)
{
    const int idx = blockIdx.x * 256 + threadIdx.x;
    g_Wt[idx] = __float2half_rn(src[idx]);
}
__global__ __launch_bounds__(256) void build_wc(
    const float* __restrict__ U_iou, const float* __restrict__ U_f_w)
{
    const int idx = blockIdx.x * 256 + threadIdx.x;
    const int n = idx >> 8, k = idx & 255;
    const float v = (n < 768) ? U_iou[n * 256 + k]
                              : U_f_w[((n - 768) & 255) * 256 + k];
    g_Wc[idx] = __float2half_rn(v);
}

// ---------------------------------------------------------------------------
// Double-buffered single-pass fp16 GEMM.  C[M,N](fp16) = A[M,256] @ B[N,256]^T
// CTA tile 128x128, K = 4 chunks of 64, 2 stages x 32KB = 64KB.
// __launch_bounds__(256, 3): target <=84 regs -> 3 CTAs/SM (24 warps, 36% occ).
// MODE 0 (table): A = g_emb, B = g_Wt, C = g_table (Nc=768, 6 n-tiles)
// MODE 1 (level): tiles 0-5: A = hsum | 6,7: child0 | 8,9: child1; C = g_pre
//   LEAF=1 (level 8): child A rows gathered from g_hleaf via types.
// ---------------------------------------------------------------------------
#define SM_A  0u
#define SM_B  16384u
#define STGS  32768u
#define L_SMT 65536

template<int MODE, int LEAF>
__global__ __launch_bounds__(256, 3) void gemm_f16(
    int base, const int* __restrict__ types1, const int* __restrict__ types2)
{
    extern __shared__ char smem[];
    const uint32_t sb = smem_u32(smem);
    const int tid = threadIdx.x, wid = tid >> 5, lane = tid & 31;
    const int bm = blockIdx.x * 128;
    const int tile = blockIdx.y;
    const int bn = tile * 128;
    const int Nc = (MODE == 0) ? 768 : NPRE;

    // A source (fp16 plane)
    const __half* a;
    {
        const int r = bm + (tid >> 1);
        if (MODE == 0) {
            a = g_emb + (size_t)r * 256;
        } else if (tile < 6) {
            a = g_hsum + (size_t)r * 256;
        } else {
            const int s = (tile - 6) >> 1;
            const int j = r >> 8, bt = r & 255;
            const int child = 2 * (base + j) + 1 + s;
            if (LEAF) {
                const int* ty = (bt < BATCH) ? types1 + bt * NTREEN
                                             : types2 + (bt - BATCH) * NTREEN;
                a = g_hleaf + (size_t)ty[child] * 256;
            } else {
                a = g_h + ((size_t)bt * NTREEN + child) * 256;
            }
        }
        a += (tid & 1) * 32;
    }
    const __half* b = ((MODE == 0) ? g_Wt : g_Wc)
                      + (size_t)(bn + (tid >> 1)) * 256 + (tid & 1) * 32;

    const uint32_t rowoff = (uint32_t)(tid >> 1) * 128u;
    const uint32_t rxor   = (uint32_t)(((tid >> 1) & 7) << 4);

    #define LOADC(s, k0) do {                                                  \
        const uint32_t st_ = sb + (uint32_t)(s) * STGS;                        \
        _Pragma("unroll")                                                      \
        for (int j = 0; j < 4; j++) {                                          \
            const uint32_t xo = (uint32_t)((tid & 1) * 64 + j * 16) ^ rxor;    \
            const uint32_t d = rowoff + xo;                                    \
            CP16(st_ + SM_A + d, a + (k0) + j * 8);                            \
            CP16(st_ + SM_B + d, b + (k0) + j * 8);                            \
        }                                                                      \
    } while (0)

    const int wm = (wid & 1) * 64;
    const int wn = (wid >> 1) * 32;
    float acc[4][4][4] = {};

    LOADC(0, 0);
    CP_COMMIT();

    #pragma unroll 1
    for (int kc = 0; kc < 4; kc++) {
        if (kc < 3) {
            LOADC((kc + 1) & 1, (kc + 1) * 64);
            CP_COMMIT();
            CP_WAIT1();
        } else {
            CP_WAIT0();
        }
        __syncthreads();

        const uint32_t st = sb + (uint32_t)(kc & 1) * STGS;
        #pragma unroll
        for (int kg = 0; kg < 4; kg++) {
            uint32_t bf[4][2];
            #pragma unroll
            for (int nf = 0; nf < 4; nf++) {
                const uint32_t nrow = (uint32_t)(wn + nf * 8 + (lane & 7));
                const uint32_t x = (uint32_t)(kg * 32 + ((lane >> 3) & 1) * 16);
                const uint32_t sw = nrow * 128u + (x ^ ((nrow & 7u) << 4));
                ldm_x2(bf[nf], st + SM_B + sw);
            }
            #pragma unroll
            for (int mf = 0; mf < 4; mf++) {
                const uint32_t mrow = (uint32_t)(wm + mf * 16 + (lane & 15));
                const uint32_t x = (uint32_t)(kg * 32 + (lane >> 4) * 16);
                const uint32_t sw = mrow * 128u + (x ^ ((mrow & 7u) << 4));
                uint32_t a4[4];
                ldm_x4(a4, st + SM_A + sw);
                #pragma unroll
                for (int nf = 0; nf < 4; nf++)
                    mma_f16(acc[mf][nf], a4, bf[nf]);
            }
        }
        __syncthreads();
    }
    #undef LOADC

    __half* __restrict__ C = (MODE == 0) ? g_table : g_pre;
    #pragma unroll
    for (int mf = 0; mf < 4; mf++) {
        const int row = bm + wm + mf * 16 + (lane >> 2);
        #pragma unroll
        for (int nf = 0; nf < 4; nf++) {
            const int col = bn + wn + nf * 8 + (lane & 3) * 2;
            *(__half2*)&C[(size_t)row * Nc + col] =
                __floats2half2_rn(acc[mf][nf][0], acc[mf][nf][1]);
            *(__half2*)&C[(size_t)(row + 8) * Nc + col] =
                __floats2half2_rn(acc[mf][nf][2], acc[mf][nf][3]);
        }
    }
}

// ---------------------------------------------------------------------------
// Vocab leaf precompute: per-vocab leaf h (fp16) and c (fp32).
// ---------------------------------------------------------------------------
__global__ __launch_bounds__(256) void vocab_leaf(const float* __restrict__ b_iou)
{
    const int t   = blockIdx.x * 256 + threadIdx.x;
    const int hs4 = t & 63;
    const int v   = t >> 6;

    const float4* bb = (const float4*)b_iou;
    const float4 b0 = bb[hs4], b1 = bb[64 + hs4], b2 = bb[128 + hs4];

    const __half2* t2 = (const __half2*)(g_table + (size_t)v * 768);
    const float4 i4 = ldh4(t2 + hs4 * 2);
    const float4 o4 = ldh4(t2 + 128 + hs4 * 2);
    const float4 u4 = ldh4(t2 + 256 + hs4 * 2);

    float4 cn; float hv[4];
    #define DOLANE(c_, e_)                                       \
    {   float cv = sigf(i4.c_ + b0.c_) * tanhf_(u4.c_ + b2.c_);  \
        cn.c_ = cv;                                              \
        hv[e_] = sigf(o4.c_ + b1.c_) * tanhf_(cv); }
    DOLANE(x, 0) DOLANE(y, 1) DOLANE(z, 2) DOLANE(w, 3)
    #undef DOLANE

    ((float4*)(g_cleaf + (size_t)v * 256))[hs4] = cn;
    ((uint2*)(g_hleaf + (size_t)v * 256))[hs4]  = pack_h4(hv);
}

// ---------------------------------------------------------------------------
// Leaf hsum only: hsum[pair] = hleaf[types[left]] + hleaf[types[right]].
// ---------------------------------------------------------------------------
__global__ __launch_bounds__(256) void leaf_hsum(
    const int* __restrict__ types1, const int* __restrict__ types2)
{
    const int tid = blockIdx.x * 256 + threadIdx.x;
    const int hs4 = tid & 63;
    const int q   = tid >> 6;
    const int bt  = q & 255;
    const int tp  = q >> 8;              // pair 0..255

    const int* ty = (bt < BATCH) ? types1 + bt * NTREEN
                                 : types2 + (bt - BATCH) * NTREEN;
    const int v0 = ty[511 + 2 * tp];
    const int v1 = ty[511 + 2 * tp + 1];

    const float4 h0 = unp_h4(((const uint2*)(g_hleaf + (size_t)v0 * 256))[hs4]);
    const float4 h1 = unp_h4(((const uint2*)(g_hleaf + (size_t)v1 * 256))[hs4]);

    float hs[4] = { h0.x + h1.x, h0.y + h1.y, h0.z + h1.z, h0.w + h1.w };
    ((uint2*)(g_hsum + (size_t)(tp * 256 + bt) * 256))[hs4] = pack_h4(hs);
}

// ---------------------------------------------------------------------------
// Internal-level elementwise, fused sibling pair + hsum.
// LEAF=1 (level 8): children c gathered from g_cleaf via types (fp32).
// LEAF=0: children c from g_c16 (fp16).
// ---------------------------------------------------------------------------
template<int LEAF>
__global__ __launch_bounds__(256) void level_ew_pair(
    const float* __restrict__ b_iou, const float* __restrict__ U_f_b, int cbase,
    const int* __restrict__ types1, const int* __restrict__ types2)
{
    const int tid = blockIdx.x * 256 + threadIdx.x;
    const int hs4 = tid & 63;
    const int q   = tid >> 6;
    const int bt  = q & 255;
    const int tp  = q >> 8;

    const float4* bb = (const float4*)b_iou;
    const float4 b0 = bb[hs4], b1 = bb[64 + hs4], b2 = bb[128 + hs4];
    const float4 fb = ((const float4*)U_f_b)[hs4];

    const int* ty = (bt < BATCH) ? types1 + bt * NTREEN
                                 : types2 + (bt - BATCH) * NTREEN;

    float hsum[4] = {0.f, 0.f, 0.f, 0.f};
    #pragma unroll
    for (int s = 0; s < 2; s++) {
        const int node = cbase + 2 * tp + s;
        const int i    = (2 * tp + s) * 256 + bt;

        float4 c0, c1;
        if (LEAF) {
            const int v0 = ty[2 * node + 1];
            const int v1 = ty[2 * node + 2];
            c0 = ((const float4*)(g_cleaf + (size_t)v0 * 256))[hs4];
            c1 = ((const float4*)(g_cleaf + (size_t)v1 * 256))[hs4];
        } else {
            const size_t rc0 = ((size_t)bt * NTREEN + 2 * node + 1) * 256;
            c0 = unp_h4(((const uint2*)(g_c16 + rc0))[hs4]);
            c1 = unp_h4(((const uint2*)(g_c16 + rc0 + 256))[hs4]);
        }

        const __half2* p2 = (const __half2*)(g_pre + (size_t)i * NPRE);
        const float4 iI = ldh4(p2 + hs4 * 2);
        const float4 iO = ldh4(p2 + 128 + hs4 * 2);
        const float4 iU = ldh4(p2 + 256 + hs4 * 2);
        const float4 f0 = ldh4(p2 + 384 + hs4 * 2);
        const float4 f1 = ldh4(p2 + 512 + hs4 * 2);

        float cnv[4]; float hv[4];
        #define DOLANE(c_, e_)                                                      \
        {   float csum = sigf(f0.c_ + fb.c_) * c0.c_ + sigf(f1.c_ + fb.c_) * c1.c_; \
            float cv = sigf(iI.c_ + b0.c_) * tanhf_(iU.c_ + b2.c_) + csum;          \
            cnv[e_] = cv;                                                           \
            hv[e_] = sigf(iO.c_ + b1.c_) * tanhf_(cv);                              \
            hsum[e_] += hv[e_]; }
        DOLANE(x, 0) DOLANE(y, 1) DOLANE(z, 2) DOLANE(w, 3)
        #undef DOLANE

        const size_t rowoff = ((size_t)bt * NTREEN + node) * 256;
        ((uint2*)(g_c16 + rowoff))[hs4] = pack_h4(cnv);
        ((uint2*)(g_h + rowoff))[hs4]   = pack_h4(hv);
    }
    ((uint2*)(g_hsum + (size_t)(tp * 256 + bt) * 256))[hs4] = pack_h4(hsum);
}

// ---------------------------------------------------------------------------
// Root elementwise (node 0, no hsum)
// ---------------------------------------------------------------------------
__global__ __launch_bounds__(256) void level_ew_root(
    const float* __restrict__ b_iou, const float* __restrict__ U_f_b)
{
    const int tid = blockIdx.x * 256 + threadIdx.x;
    const int hs4 = tid & 63;
    const int bt  = tid >> 6;

    const size_t rc0 = ((size_t)bt * NTREEN + 1) * 256;
    const float4 c0 = unp_h4(((const uint2*)(g_c16 + rc0))[hs4]);
    const float4 c1 = unp_h4(((const uint2*)(g_c16 + rc0 + 256))[hs4]);

    const __half2* p2 = (const __half2*)(g_pre + (size_t)bt * NPRE);
    const float4 iI = ldh4(p2 + hs4 * 2);
    const float4 iO = ldh4(p2 + 128 + hs4 * 2);
    const float4 iU = ldh4(p2 + 256 + hs4 * 2);
    const float4 f0 = ldh4(p2 + 384 + hs4 * 2);
    const float4 f1 = ldh4(p2 + 512 + hs4 * 2);

    const float4* bb = (const float4*)b_iou;
    const float4 b0 = bb[hs4], b1 = bb[64 + hs4], b2 = bb[128 + hs4];
    const float4 fb = ((const float4*)U_f_b)[hs4];

    float cnv[4]; float hv[4];
    #define DOLANE(c_, e_)                                                      \
    {   float csum = sigf(f0.c_ + fb.c_) * c0.c_ + sigf(f1.c_ + fb.c_) * c1.c_; \
        float cv = sigf(iI.c_ + b0.c_) * tanhf_(iU.c_ + b2.c_) + csum;          \
        cnv[e_] = cv;                                                           \
        hv[e_] = sigf(iO.c_ + b1.c_) * tanhf_(cv); }
    DOLANE(x, 0) DOLANE(y, 1) DOLANE(z, 2) DOLANE(w, 3)
    #undef DOLANE

    const size_t rowoff = (size_t)bt * NTREEN * 256;
    ((uint2*)(g_c16 + rowoff))[hs4] = pack_h4(cnv);
    ((uint2*)(g_h + rowoff))[hs4]   = pack_h4(hv);
}

// ---------------------------------------------------------------------------
// Final classifier: internal nodes from g_h, leaves gathered via types.
// ---------------------------------------------------------------------------
__global__ __launch_bounds__(256) void final_k(
    const int* __restrict__ types1, const int* __restrict__ types2,
    const float* __restrict__ cls_w, const float* __restrict__ cls_b,
    float* __restrict__ out)
{
    const int b  = blockIdx.x;
    const int hs = threadIdx.x;

    const size_t o1 = (size_t)b           * NTREEN * 256 + hs;
    const size_t o2 = (size_t)(b + BATCH) * NTREEN * 256 + hs;
    const int* ty1 = types1 + b * NTREEN;
    const int* ty2 = types2 + b * NTREEN;

    float s1 = 0.f, s2 = 0.f;
    #pragma unroll 4
    for (int n = 0; n < 511; n++) {
        s1 += __half2float(g_h[o1 + (size_t)n * 256]);
        s2 += __half2float(g_h[o2 + (size_t)n * 256]);
    }
    #pragma unroll 4
    for (int n = 511; n < NTREEN; n++) {
        s1 += __half2float(g_hleaf[(size_t)ty1[n] * 256 + hs]);
        s2 += __half2float(g_hleaf[(size_t)ty2[n] * 256 + hs]);
    }
    const float d = fabsf(s1 - s2) * (1.0f / (float)NTREEN);

    float v0 = d * cls_w[hs];
    float v1 = d * cls_w[256 + hs];

    #pragma unroll
    for (int off = 16; off > 0; off >>= 1) {
        v0 += __shfl_down_sync(0xffffffffu, v0, off);
        v1 += __shfl_down_sync(0xffffffffu, v1, off);
    }
    __shared__ float sm0[8], sm1[8];
    const int w = threadIdx.x >> 5, lane = threadIdx.x & 31;
    if (lane == 0) { sm0[w] = v0; sm1[w] = v1; }
    __syncthreads();
    if (threadIdx.x == 0) {
        float t0 = 0.f, t1 = 0.f;
        #pragma unroll
        for (int k = 0; k < 8; k++) { t0 += sm0[k]; t1 += sm1[k]; }
        out[b * 2 + 0] = t0 + cls_b[0];
        out[b * 2 + 1] = t1 + cls_b[1];
    }
}

// ---------------------------------------------------------------------------
// Launch
// ---------------------------------------------------------------------------
extern "C" void kernel_launch(void* const* d_in, const int* in_sizes, int n_in,
                              void* d_out, int out_size)
{
    (void)in_sizes; (void)n_in; (void)out_size;
    const int*   types1 = (const int*)  d_in[0];
    const int*   types2 = (const int*)  d_in[1];
    const float* emb    = (const float*)d_in[2];
    const float* W_iou  = (const float*)d_in[3];
    const float* U_iou  = (const float*)d_in[4];
    const float* b_iou  = (const float*)d_in[5];
    const float* U_f_w  = (const float*)d_in[6];
    const float* U_f_b  = (const float*)d_in[7];
    const float* cls_w  = (const float*)d_in[8];
    const float* cls_b  = (const float*)d_in[9];
    float* out = (float*)d_out;

    cudaFuncSetAttribute(gemm_f16<0,0>, cudaFuncAttributeMaxDynamicSharedMemorySize, L_SMT);
    cudaFuncSetAttribute(gemm_f16<1,0>, cudaFuncAttributeMaxDynamicSharedMemorySize, L_SMT);
    cudaFuncSetAttribute(gemm_f16<1,1>, cudaFuncAttributeMaxDynamicSharedMemorySize, L_SMT);

    // 0) prep: fp16 conversions
    emb_f16<<<VOCABN, 256>>>(emb);
    wt_f16<<<768, 256>>>(W_iou);
    build_wc<<<NPRE, 256>>>(U_iou, U_f_w);

    // 1) vocab table + per-vocab leaf h/c
    gemm_f16<0,0><<<dim3(VOCABN / 128, 6), 256, L_SMT>>>(0, nullptr, nullptr);
    vocab_leaf<<<VOCABN / 4, 256>>>(b_iou);

    // 2) leaf hsum (only materialization needed for leaves)
    leaf_hsum<<<16384, 256>>>(types1, types2);

    // 3) level 8 (children = leaves, gathered via types)
    {
        const int base = 255;
        gemm_f16<1,1><<<dim3((BTN << 8) / 128, 10), 256, L_SMT>>>(base, types1, types2);
        level_ew_pair<1><<<64 << 7, 256>>>(b_iou, U_f_b, base, types1, types2);
    }

    // 4) internal levels 7..1
    for (int lvl = 7; lvl >= 1; --lvl) {
        const int base = (1 << lvl) - 1;
        gemm_f16<1,0><<<dim3((BTN << lvl) / 128, 10), 256, L_SMT>>>(base, nullptr, nullptr);
        level_ew_pair<0><<<64 << (lvl - 1), 256>>>(b_iou, U_f_b, base, types1, types2);
    }

    // 5) root level
    gemm_f16<1,0><<<dim3(2, 10), 256, L_SMT>>>(0, nullptr, nullptr);
    level_ew_root<<<64, 256>>>(b_iou, U_f_b);

    // 6) classifier
    final_k<<<BATCH, 256>>>(types1, types2, cls_w, cls_b, out);
}

// round 16
// speedup vs baseline: 1.3595x; 1.3595x over previous
#include <cuda_runtime.h>
#include <cuda_fp16.h>
#include <stdint.h>
#include <math.h>

// ---------------------------------------------------------------------------
// Problem constants
// ---------------------------------------------------------------------------
#define VOCABN 32000
#define BATCH  128
#define BTN    256          // 2*BATCH
#define NTREEN 1023
#define NPRE   1280         // iou(768) | f0(256) | f1(256)

// ---------------------------------------------------------------------------
// Scratch (device globals)
// ---------------------------------------------------------------------------
__device__ __align__(16) __half g_emb  [(size_t)VOCABN * 256];
__device__ __align__(16) __half g_Wt   [768 * 256];
__device__ __align__(16) __half g_Wc   [NPRE * 256];
__device__ __align__(16) __half g_table[(size_t)VOCABN * 768];
__device__ __align__(16) __half g_hleaf[(size_t)VOCABN * 256];   // leaf h per vocab
__device__ __align__(16) float  g_cleaf[(size_t)VOCABN * 256];   // leaf c per vocab (fp32)
__device__ __align__(16) __half g_h    [(size_t)BTN * NTREEN * 256];  // internal nodes
__device__ __align__(16) __half g_c16  [(size_t)BTN * NTREEN * 256];  // internal c, fp16
__device__ __align__(16) __half g_hsum [(size_t)65536 * 256];
__device__ __align__(16) __half g_pre  [(size_t)65536 * NPRE];
__device__ __align__(16) float2 g_fpart[(size_t)BATCH * 8 * 256];    // final partials

// ---------------------------------------------------------------------------
// Helpers
// ---------------------------------------------------------------------------
__device__ __forceinline__ float sigf(float x)   { return 1.0f / (1.0f + __expf(-x)); }
__device__ __forceinline__ float tanhf_(float x) { return 2.0f / (1.0f + __expf(-2.0f * x)) - 1.0f; }

__device__ __forceinline__ uint32_t smem_u32(const void* p) {
    uint32_t a;
    asm("{ .reg .u64 t; cvta.to.shared.u64 t, %1; cvt.u32.u64 %0, t; }" : "=r"(a) : "l"(p));
    return a;
}
__device__ __forceinline__ float4 ldh4(const __half2* p) {
    __half2 a = p[0], b = p[1];
    return make_float4(__low2float(a), __high2float(a),
                       __low2float(b), __high2float(b));
}
__device__ __forceinline__ float4 unp_h4(uint2 u) {
    return make_float4(
        __half2float(__ushort_as_half((unsigned short)(u.x & 0xFFFF))),
        __half2float(__ushort_as_half((unsigned short)(u.x >> 16))),
        __half2float(__ushort_as_half((unsigned short)(u.y & 0xFFFF))),
        __half2float(__ushort_as_half((unsigned short)(u.y >> 16))));
}
__device__ __forceinline__ uint2 pack_h4(const float h[4]) {
    unsigned short b[4];
    #pragma unroll
    for (int e = 0; e < 4; e++) b[e] = __half_as_ushort(__float2half_rn(h[e]));
    return make_uint2(b[0] | ((unsigned)b[1] << 16), b[2] | ((unsigned)b[3] << 16));
}

// ---------------------------------------------------------------------------
// Baseline-PTX tensor ops + cp.async
// ---------------------------------------------------------------------------
__device__ __forceinline__ void ldm_x4(uint32_t r[4], uint32_t addr) {
    asm volatile("ldmatrix.sync.aligned.m8n8.x4.shared.b16 {%0,%1,%2,%3}, [%4];"
        : "=r"(r[0]), "=r"(r[1]), "=r"(r[2]), "=r"(r[3]) : "r"(addr));
}
__device__ __forceinline__ void ldm_x2(uint32_t r[2], uint32_t addr) {
    asm volatile("ldmatrix.sync.aligned.m8n8.x2.shared.b16 {%0,%1}, [%2];"
        : "=r"(r[0]), "=r"(r[1]) : "r"(addr));
}
__device__ __forceinline__ void mma_f16(float c[4], const uint32_t a[4], const uint32_t b[2]) {
    asm volatile("mma.sync.aligned.m16n8k16.row.col.f32.f16.f16.f32 "
        "{%0,%1,%2,%3}, {%4,%5,%6,%7}, {%8,%9}, {%0,%1,%2,%3};"
        : "+f"(c[0]), "+f"(c[1]), "+f"(c[2]), "+f"(c[3])
        : "r"(a[0]), "r"(a[1]), "r"(a[2]), "r"(a[3]), "r"(b[0]), "r"(b[1]));
}
#define CP16(dst, src) asm volatile("cp.async.cg.shared.global [%0], [%1], 16;" :: "r"(dst), "l"(src))
#define CP_COMMIT()    asm volatile("cp.async.commit_group;" ::: "memory")
#define CP_WAIT1()     asm volatile("cp.async.wait_group 1;" ::: "memory")
#define CP_WAIT0()     asm volatile("cp.async.wait_group 0;" ::: "memory")

// ---------------------------------------------------------------------------
// Prep kernels
// ---------------------------------------------------------------------------
__global__ __launch_bounds__(256) void emb_f16(const float* __restrict__ src)
{
    const int idx = blockIdx.x * 256 + threadIdx.x;
    g_emb[idx] = __float2half_rn(src[idx]);
}
__global__ __launch_bounds__(256) void wt_f16(const float* __restrict__ src)
{
    const int idx = blockIdx.x * 256 + threadIdx.x;
    g_Wt[idx] = __float2half_rn(src[idx]);
}
__global__ __launch_bounds__(256) void build_wc(
    const float* __restrict__ U_iou, const float* __restrict__ U_f_w)
{
    const int idx = blockIdx.x * 256 + threadIdx.x;
    const int n = idx >> 8, k = idx & 255;
    const float v = (n < 768) ? U_iou[n * 256 + k]
                              : U_f_w[((n - 768) & 255) * 256 + k];
    g_Wc[idx] = __float2half_rn(v);
}

// ---------------------------------------------------------------------------
// Double-buffered single-pass fp16 GEMM (R14 proven config: 256 thr, 2 CTA/SM,
// 128 regs = ptxas software pipelining).  C[M,N](fp16) = A[M,256] @ B[N,256]^T
// CTA tile 128x128, K = 4 chunks of 64, 2 stages x 32KB = 64KB.
// MODE 0 (table): A = g_emb, B = g_Wt, C = g_table (Nc=768, 6 n-tiles)
// MODE 1 (level): tiles 0-5: A = hsum | 6,7: child0 | 8,9: child1; C = g_pre
//   LEAF=1 (level 8): child A rows gathered from g_hleaf via types.
// ---------------------------------------------------------------------------
#define SM_A  0u
#define SM_B  16384u
#define STGS  32768u
#define L_SMT 65536

template<int MODE, int LEAF>
__global__ __launch_bounds__(256, 2) void gemm_f16(
    int base, const int* __restrict__ types1, const int* __restrict__ types2)
{
    extern __shared__ char smem[];
    const uint32_t sb = smem_u32(smem);
    const int tid = threadIdx.x, wid = tid >> 5, lane = tid & 31;
    const int bm = blockIdx.x * 128;
    const int tile = blockIdx.y;
    const int bn = tile * 128;
    const int Nc = (MODE == 0) ? 768 : NPRE;

    // A source (fp16 plane)
    const __half* a;
    {
        const int r = bm + (tid >> 1);
        if (MODE == 0) {
            a = g_emb + (size_t)r * 256;
        } else if (tile < 6) {
            a = g_hsum + (size_t)r * 256;
        } else {
            const int s = (tile - 6) >> 1;
            const int j = r >> 8, bt = r & 255;
            const int child = 2 * (base + j) + 1 + s;
            if (LEAF) {
                const int* ty = (bt < BATCH) ? types1 + bt * NTREEN
                                             : types2 + (bt - BATCH) * NTREEN;
                a = g_hleaf + (size_t)ty[child] * 256;
            } else {
                a = g_h + ((size_t)bt * NTREEN + child) * 256;
            }
        }
        a += (tid & 1) * 32;
    }
    const __half* b = ((MODE == 0) ? g_Wt : g_Wc)
                      + (size_t)(bn + (tid >> 1)) * 256 + (tid & 1) * 32;

    const uint32_t rowoff = (uint32_t)(tid >> 1) * 128u;
    const uint32_t rxor   = (uint32_t)(((tid >> 1) & 7) << 4);

    #define LOADC(s, k0) do {                                                  \
        const uint32_t st_ = sb + (uint32_t)(s) * STGS;                        \
        _Pragma("unroll")                                                      \
        for (int j = 0; j < 4; j++) {                                          \
            const uint32_t xo = (uint32_t)((tid & 1) * 64 + j * 16) ^ rxor;    \
            const uint32_t d = rowoff + xo;                                    \
            CP16(st_ + SM_A + d, a + (k0) + j * 8);                            \
            CP16(st_ + SM_B + d, b + (k0) + j * 8);                            \
        }                                                                      \
    } while (0)

    const int wm = (wid & 1) * 64;
    const int wn = (wid >> 1) * 32;
    float acc[4][4][4] = {};

    LOADC(0, 0);
    CP_COMMIT();

    #pragma unroll 1
    for (int kc = 0; kc < 4; kc++) {
        if (kc < 3) {
            LOADC((kc + 1) & 1, (kc + 1) * 64);
            CP_COMMIT();
            CP_WAIT1();
        } else {
            CP_WAIT0();
        }
        __syncthreads();

        const uint32_t st = sb + (uint32_t)(kc & 1) * STGS;
        #pragma unroll
        for (int kg = 0; kg < 4; kg++) {
            uint32_t bf[4][2];
            #pragma unroll
            for (int nf = 0; nf < 4; nf++) {
                const uint32_t nrow = (uint32_t)(wn + nf * 8 + (lane & 7));
                const uint32_t x = (uint32_t)(kg * 32 + ((lane >> 3) & 1) * 16);
                const uint32_t sw = nrow * 128u + (x ^ ((nrow & 7u) << 4));
                ldm_x2(bf[nf], st + SM_B + sw);
            }
            #pragma unroll
            for (int mf = 0; mf < 4; mf++) {
                const uint32_t mrow = (uint32_t)(wm + mf * 16 + (lane & 15));
                const uint32_t x = (uint32_t)(kg * 32 + (lane >> 4) * 16);
                const uint32_t sw = mrow * 128u + (x ^ ((mrow & 7u) << 4));
                uint32_t a4[4];
                ldm_x4(a4, st + SM_A + sw);
                #pragma unroll
                for (int nf = 0; nf < 4; nf++)
                    mma_f16(acc[mf][nf], a4, bf[nf]);
            }
        }
        __syncthreads();
    }
    #undef LOADC

    __half* __restrict__ C = (MODE == 0) ? g_table : g_pre;
    #pragma unroll
    for (int mf = 0; mf < 4; mf++) {
        const int row = bm + wm + mf * 16 + (lane >> 2);
        #pragma unroll
        for (int nf = 0; nf < 4; nf++) {
            const int col = bn + wn + nf * 8 + (lane & 3) * 2;
            *(__half2*)&C[(size_t)row * Nc + col] =
                __floats2half2_rn(acc[mf][nf][0], acc[mf][nf][1]);
            *(__half2*)&C[(size_t)(row + 8) * Nc + col] =
                __floats2half2_rn(acc[mf][nf][2], acc[mf][nf][3]);
        }
    }
}

// ---------------------------------------------------------------------------
// Vocab leaf precompute: per-vocab leaf h (fp16) and c (fp32).
// ---------------------------------------------------------------------------
__global__ __launch_bounds__(256) void vocab_leaf(const float* __restrict__ b_iou)
{
    const int t   = blockIdx.x * 256 + threadIdx.x;
    const int hs4 = t & 63;
    const int v   = t >> 6;

    const float4* bb = (const float4*)b_iou;
    const float4 b0 = bb[hs4], b1 = bb[64 + hs4], b2 = bb[128 + hs4];

    const __half2* t2 = (const __half2*)(g_table + (size_t)v * 768);
    const float4 i4 = ldh4(t2 + hs4 * 2);
    const float4 o4 = ldh4(t2 + 128 + hs4 * 2);
    const float4 u4 = ldh4(t2 + 256 + hs4 * 2);

    float4 cn; float hv[4];
    #define DOLANE(c_, e_)                                       \
    {   float cv = sigf(i4.c_ + b0.c_) * tanhf_(u4.c_ + b2.c_);  \
        cn.c_ = cv;                                              \
        hv[e_] = sigf(o4.c_ + b1.c_) * tanhf_(cv); }
    DOLANE(x, 0) DOLANE(y, 1) DOLANE(z, 2) DOLANE(w, 3)
    #undef DOLANE

    ((float4*)(g_cleaf + (size_t)v * 256))[hs4] = cn;
    ((uint2*)(g_hleaf + (size_t)v * 256))[hs4]  = pack_h4(hv);
}

// ---------------------------------------------------------------------------
// Leaf hsum: hsum[pair] = hleaf[types[left]] + hleaf[types[right]].
// ---------------------------------------------------------------------------
__global__ __launch_bounds__(256) void leaf_hsum(
    const int* __restrict__ types1, const int* __restrict__ types2)
{
    const int tid = blockIdx.x * 256 + threadIdx.x;
    const int hs4 = tid & 63;
    const int q   = tid >> 6;
    const int bt  = q & 255;
    const int tp  = q >> 8;

    const int* ty = (bt < BATCH) ? types1 + bt * NTREEN
                                 : types2 + (bt - BATCH) * NTREEN;
    const int v0 = ty[511 + 2 * tp];
    const int v1 = ty[511 + 2 * tp + 1];

    const float4 h0 = unp_h4(((const uint2*)(g_hleaf + (size_t)v0 * 256))[hs4]);
    const float4 h1 = unp_h4(((const uint2*)(g_hleaf + (size_t)v1 * 256))[hs4]);

    float hs[4] = { h0.x + h1.x, h0.y + h1.y, h0.z + h1.z, h0.w + h1.w };
    ((uint2*)(g_hsum + (size_t)(tp * 256 + bt) * 256))[hs4] = pack_h4(hs);
}

// ---------------------------------------------------------------------------
// Internal-level elementwise, fused sibling pair + hsum.
// LEAF=1 (level 8): children c gathered from g_cleaf via types.
// ---------------------------------------------------------------------------
template<int LEAF>
__global__ __launch_bounds__(256) void level_ew_pair(
    const float* __restrict__ b_iou, const float* __restrict__ U_f_b, int cbase,
    const int* __restrict__ types1, const int* __restrict__ types2)
{
    const int tid = blockIdx.x * 256 + threadIdx.x;
    const int hs4 = tid & 63;
    const int q   = tid >> 6;
    const int bt  = q & 255;
    const int tp  = q >> 8;

    const float4* bb = (const float4*)b_iou;
    const float4 b0 = bb[hs4], b1 = bb[64 + hs4], b2 = bb[128 + hs4];
    const float4 fb = ((const float4*)U_f_b)[hs4];

    const int* ty = (bt < BATCH) ? types1 + bt * NTREEN
                                 : types2 + (bt - BATCH) * NTREEN;

    float hsum[4] = {0.f, 0.f, 0.f, 0.f};
    #pragma unroll
    for (int s = 0; s < 2; s++) {
        const int node = cbase + 2 * tp + s;
        const int i    = (2 * tp + s) * 256 + bt;

        float4 c0, c1;
        if (LEAF) {
            const int v0 = ty[2 * node + 1];
            const int v1 = ty[2 * node + 2];
            c0 = ((const float4*)(g_cleaf + (size_t)v0 * 256))[hs4];
            c1 = ((const float4*)(g_cleaf + (size_t)v1 * 256))[hs4];
        } else {
            const size_t rc0 = ((size_t)bt * NTREEN + 2 * node + 1) * 256;
            c0 = unp_h4(((const uint2*)(g_c16 + rc0))[hs4]);
            c1 = unp_h4(((const uint2*)(g_c16 + rc0 + 256))[hs4]);
        }

        const __half2* p2 = (const __half2*)(g_pre + (size_t)i * NPRE);
        const float4 iI = ldh4(p2 + hs4 * 2);
        const float4 iO = ldh4(p2 + 128 + hs4 * 2);
        const float4 iU = ldh4(p2 + 256 + hs4 * 2);
        const float4 f0 = ldh4(p2 + 384 + hs4 * 2);
        const float4 f1 = ldh4(p2 + 512 + hs4 * 2);

        float cnv[4]; float hv[4];
        #define DOLANE(c_, e_)                                                      \
        {   float csum = sigf(f0.c_ + fb.c_) * c0.c_ + sigf(f1.c_ + fb.c_) * c1.c_; \
            float cv = sigf(iI.c_ + b0.c_) * tanhf_(iU.c_ + b2.c_) + csum;          \
            cnv[e_] = cv;                                                           \
            hv[e_] = sigf(iO.c_ + b1.c_) * tanhf_(cv);                              \
            hsum[e_] += hv[e_]; }
        DOLANE(x, 0) DOLANE(y, 1) DOLANE(z, 2) DOLANE(w, 3)
        #undef DOLANE

        const size_t rowoff = ((size_t)bt * NTREEN + node) * 256;
        ((uint2*)(g_c16 + rowoff))[hs4] = pack_h4(cnv);
        ((uint2*)(g_h + rowoff))[hs4]   = pack_h4(hv);
    }
    ((uint2*)(g_hsum + (size_t)(tp * 256 + bt) * 256))[hs4] = pack_h4(hsum);
}

// ---------------------------------------------------------------------------
// Root elementwise (node 0, no hsum)
// ---------------------------------------------------------------------------
__global__ __launch_bounds__(256) void level_ew_root(
    const float* __restrict__ b_iou, const float* __restrict__ U_f_b)
{
    const int tid = blockIdx.x * 256 + threadIdx.x;
    const int hs4 = tid & 63;
    const int bt  = tid >> 6;

    const size_t rc0 = ((size_t)bt * NTREEN + 1) * 256;
    const float4 c0 = unp_h4(((const uint2*)(g_c16 + rc0))[hs4]);
    const float4 c1 = unp_h4(((const uint2*)(g_c16 + rc0 + 256))[hs4]);

    const __half2* p2 = (const __half2*)(g_pre + (size_t)bt * NPRE);
    const float4 iI = ldh4(p2 + hs4 * 2);
    const float4 iO = ldh4(p2 + 128 + hs4 * 2);
    const float4 iU = ldh4(p2 + 256 + hs4 * 2);
    const float4 f0 = ldh4(p2 + 384 + hs4 * 2);
    const float4 f1 = ldh4(p2 + 512 + hs4 * 2);

    const float4* bb = (const float4*)b_iou;
    const float4 b0 = bb[hs4], b1 = bb[64 + hs4], b2 = bb[128 + hs4];
    const float4 fb = ((const float4*)U_f_b)[hs4];

    float cnv[4]; float hv[4];
    #define DOLANE(c_, e_)                                                      \
    {   float csum = sigf(f0.c_ + fb.c_) * c0.c_ + sigf(f1.c_ + fb.c_) * c1.c_; \
        float cv = sigf(iI.c_ + b0.c_) * tanhf_(iU.c_ + b2.c_) + csum;          \
        cnv[e_] = cv;                                                           \
        hv[e_] = sigf(iO.c_ + b1.c_) * tanhf_(cv); }
    DOLANE(x, 0) DOLANE(y, 1) DOLANE(z, 2) DOLANE(w, 3)
    #undef DOLANE

    const size_t rowoff = (size_t)bt * NTREEN * 256;
    ((uint2*)(g_c16 + rowoff))[hs4] = pack_h4(cnv);
    ((uint2*)(g_h + rowoff))[hs4]   = pack_h4(hv);
}

// ---------------------------------------------------------------------------
// Final stage 1: 8 partial-sum blocks per batch row (8x the parallelism).
// Block (b, chunk) sums nodes [chunk*128, min(chunk*128+128, 1023)).
// ---------------------------------------------------------------------------
__global__ __launch_bounds__(256) void final_part(
    const int* __restrict__ types1, const int* __restrict__ types2)
{
    const int b     = blockIdx.x >> 3;
    const int chunk = blockIdx.x & 7;
    const int hs    = threadIdx.x;

    const int n0 = chunk * 128;
    const int n1 = (chunk == 7) ? NTREEN : n0 + 128;

    const size_t o1 = (size_t)b           * NTREEN * 256 + hs;
    const size_t o2 = (size_t)(b + BATCH) * NTREEN * 256 + hs;
    const int* ty1 = types1 + b * NTREEN;
    const int* ty2 = types2 + b * NTREEN;

    float s1 = 0.f, s2 = 0.f;
    for (int n = n0; n < n1; n++) {
        if (n < 511) {
            s1 += __half2float(g_h[o1 + (size_t)n * 256]);
            s2 += __half2float(g_h[o2 + (size_t)n * 256]);
        } else {
            s1 += __half2float(g_hleaf[(size_t)ty1[n] * 256 + hs]);
            s2 += __half2float(g_hleaf[(size_t)ty2[n] * 256 + hs]);
        }
    }
    g_fpart[(size_t)blockIdx.x * 256 + hs] = make_float2(s1, s2);
}

// ---------------------------------------------------------------------------
// Final stage 2: combine 8 partials, |diff| mean, classifier.
// ---------------------------------------------------------------------------
__global__ __launch_bounds__(256) void final_reduce(
    const float* __restrict__ cls_w, const float* __restrict__ cls_b,
    float* __restrict__ out)
{
    const int b  = blockIdx.x;
    const int hs = threadIdx.x;

    float s1 = 0.f, s2 = 0.f;
    #pragma unroll
    for (int k = 0; k < 8; k++) {
        const float2 p = g_fpart[(size_t)(b * 8 + k) * 256 + hs];
        s1 += p.x; s2 += p.y;
    }
    const float d = fabsf(s1 - s2) * (1.0f / (float)NTREEN);

    float v0 = d * cls_w[hs];
    float v1 = d * cls_w[256 + hs];

    #pragma unroll
    for (int off = 16; off > 0; off >>= 1) {
        v0 += __shfl_down_sync(0xffffffffu, v0, off);
        v1 += __shfl_down_sync(0xffffffffu, v1, off);
    }
    __shared__ float sm0[8], sm1[8];
    const int w = threadIdx.x >> 5, lane = threadIdx.x & 31;
    if (lane == 0) { sm0[w] = v0; sm1[w] = v1; }
    __syncthreads();
    if (threadIdx.x == 0) {
        float t0 = 0.f, t1 = 0.f;
        #pragma unroll
        for (int k = 0; k < 8; k++) { t0 += sm0[k]; t1 += sm1[k]; }
        out[b * 2 + 0] = t0 + cls_b[0];
        out[b * 2 + 1] = t1 + cls_b[1];
    }
}

// ---------------------------------------------------------------------------
// Launch
// ---------------------------------------------------------------------------
extern "C" void kernel_launch(void* const* d_in, const int* in_sizes, int n_in,
                              void* d_out, int out_size)
{
    (void)in_sizes; (void)n_in; (void)out_size;
    const int*   types1 = (const int*)  d_in[0];
    const int*   types2 = (const int*)  d_in[1];
    const float* emb    = (const float*)d_in[2];
    const float* W_iou  = (const float*)d_in[3];
    const float* U_iou  = (const float*)d_in[4];
    const float* b_iou  = (const float*)d_in[5];
    const float* U_f_w  = (const float*)d_in[6];
    const float* U_f_b  = (const float*)d_in[7];
    const float* cls_w  = (const float*)d_in[8];
    const float* cls_b  = (const float*)d_in[9];
    float* out = (float*)d_out;

    cudaFuncSetAttribute(gemm_f16<0,0>, cudaFuncAttributeMaxDynamicSharedMemorySize, L_SMT);
    cudaFuncSetAttribute(gemm_f16<1,0>, cudaFuncAttributeMaxDynamicSharedMemorySize, L_SMT);
    cudaFuncSetAttribute(gemm_f16<1,1>, cudaFuncAttributeMaxDynamicSharedMemorySize, L_SMT);

    // 0) prep: fp16 conversions
    emb_f16<<<VOCABN, 256>>>(emb);
    wt_f16<<<768, 256>>>(W_iou);
    build_wc<<<NPRE, 256>>>(U_iou, U_f_w);

    // 1) vocab table + per-vocab leaf h/c
    gemm_f16<0,0><<<dim3(VOCABN / 128, 6), 256, L_SMT>>>(0, nullptr, nullptr);
    vocab_leaf<<<VOCABN / 4, 256>>>(b_iou);

    // 2) leaf hsum
    leaf_hsum<<<16384, 256>>>(types1, types2);

    // 3) level 8 (children = leaves, gathered via types)
    {
        const int base = 255;
        gemm_f16<1,1><<<dim3((BTN << 8) / 128, 10), 256, L_SMT>>>(base, types1, types2);
        level_ew_pair<1><<<64 << 7, 256>>>(b_iou, U_f_b, base, types1, types2);
    }

    // 4) internal levels 7..1
    for (int lvl = 7; lvl >= 1; --lvl) {
        const int base = (1 << lvl) - 1;
        gemm_f16<1,0><<<dim3((BTN << lvl) / 128, 10), 256, L_SMT>>>(base, nullptr, nullptr);
        level_ew_pair<0><<<64 << (lvl - 1), 256>>>(b_iou, U_f_b, base, types1, types2);
    }

    // 5) root level
    gemm_f16<1,0><<<dim3(2, 10), 256, L_SMT>>>(0, nullptr, nullptr);
    level_ew_root<<<64, 256>>>(b_iou, U_f_b);

    // 6) classifier: partials (1024 CTAs) -> reduce (128 CTAs)
    final_part<<<BATCH * 8, 256>>>(types1, types2);
    final_reduce<<<BATCH, 256>>>(cls_w, cls_b, out);
}

// round 17
// speedup vs baseline: 1.4884x; 1.0948x over previous
#include <cuda_runtime.h>
#include <cuda_fp16.h>
#include <stdint.h>
#include <math.h>

// ---------------------------------------------------------------------------
// Problem constants
// ---------------------------------------------------------------------------
#define VOCABN 32000
#define BATCH  128
#define BTN    256          // 2*BATCH
#define NTREEN 1023
#define NPRE   1280         // iou(768) | f0(256) | f1(256)

// ---------------------------------------------------------------------------
// Scratch (device globals)
// ---------------------------------------------------------------------------
__device__ __align__(16) __half g_emb   [(size_t)VOCABN * 256];
__device__ __align__(16) __half g_Wt    [768 * 256];
__device__ __align__(16) __half g_Wc    [NPRE * 256];
__device__ __align__(16) __half g_table [(size_t)VOCABN * 768];
__device__ __align__(16) __half g_hleaf [(size_t)VOCABN * 256];  // leaf h per vocab
__device__ __align__(16) float  g_cleaf [(size_t)VOCABN * 256];  // leaf c per vocab
__device__ __align__(16) __half g_fpleaf[(size_t)VOCABN * 256];  // h_leaf @ U_f_w^T
__device__ __align__(16) __half g_fc    [(size_t)VOCABN * 256];  // sig(fp+fb)*c_leaf
__device__ __align__(16) __half g_h     [(size_t)BTN * NTREEN * 256];
__device__ __align__(16) __half g_c16   [(size_t)BTN * NTREEN * 256];
__device__ __align__(16) __half g_hsum  [(size_t)65536 * 256];
__device__ __align__(16) __half g_pre   [(size_t)65536 * NPRE];
__device__ __align__(16) float2 g_fpart [(size_t)BATCH * 8 * 256];

// ---------------------------------------------------------------------------
// Helpers
// ---------------------------------------------------------------------------
__device__ __forceinline__ float sigf(float x)   { return 1.0f / (1.0f + __expf(-x)); }
__device__ __forceinline__ float tanhf_(float x) { return 2.0f / (1.0f + __expf(-2.0f * x)) - 1.0f; }

__device__ __forceinline__ uint32_t smem_u32(const void* p) {
    uint32_t a;
    asm("{ .reg .u64 t; cvta.to.shared.u64 t, %1; cvt.u32.u64 %0, t; }" : "=r"(a) : "l"(p));
    return a;
}
__device__ __forceinline__ float4 ldh4(const __half2* p) {
    __half2 a = p[0], b = p[1];
    return make_float4(__low2float(a), __high2float(a),
                       __low2float(b), __high2float(b));
}
__device__ __forceinline__ float4 unp_h4(uint2 u) {
    return make_float4(
        __half2float(__ushort_as_half((unsigned short)(u.x & 0xFFFF))),
        __half2float(__ushort_as_half((unsigned short)(u.x >> 16))),
        __half2float(__ushort_as_half((unsigned short)(u.y & 0xFFFF))),
        __half2float(__ushort_as_half((unsigned short)(u.y >> 16))));
}
__device__ __forceinline__ uint2 pack_h4(const float h[4]) {
    unsigned short b[4];
    #pragma unroll
    for (int e = 0; e < 4; e++) b[e] = __half_as_ushort(__float2half_rn(h[e]));
    return make_uint2(b[0] | ((unsigned)b[1] << 16), b[2] | ((unsigned)b[3] << 16));
}

// ---------------------------------------------------------------------------
// Baseline-PTX tensor ops + cp.async
// ---------------------------------------------------------------------------
__device__ __forceinline__ void ldm_x4(uint32_t r[4], uint32_t addr) {
    asm volatile("ldmatrix.sync.aligned.m8n8.x4.shared.b16 {%0,%1,%2,%3}, [%4];"
        : "=r"(r[0]), "=r"(r[1]), "=r"(r[2]), "=r"(r[3]) : "r"(addr));
}
__device__ __forceinline__ void ldm_x2(uint32_t r[2], uint32_t addr) {
    asm volatile("ldmatrix.sync.aligned.m8n8.x2.shared.b16 {%0,%1}, [%2];"
        : "=r"(r[0]), "=r"(r[1]) : "r"(addr));
}
__device__ __forceinline__ void mma_f16(float c[4], const uint32_t a[4], const uint32_t b[2]) {
    asm volatile("mma.sync.aligned.m16n8k16.row.col.f32.f16.f16.f32 "
        "{%0,%1,%2,%3}, {%4,%5,%6,%7}, {%8,%9}, {%0,%1,%2,%3};"
        : "+f"(c[0]), "+f"(c[1]), "+f"(c[2]), "+f"(c[3])
        : "r"(a[0]), "r"(a[1]), "r"(a[2]), "r"(a[3]), "r"(b[0]), "r"(b[1]));
}
#define CP16(dst, src) asm volatile("cp.async.cg.shared.global [%0], [%1], 16;" :: "r"(dst), "l"(src))
#define CP_COMMIT()    asm volatile("cp.async.commit_group;" ::: "memory")
#define CP_WAIT1()     asm volatile("cp.async.wait_group 1;" ::: "memory")
#define CP_WAIT0()     asm volatile("cp.async.wait_group 0;" ::: "memory")

// ---------------------------------------------------------------------------
// Prep kernels
// ---------------------------------------------------------------------------
__global__ __launch_bounds__(256) void emb_f16(const float* __restrict__ src)
{
    const int idx = blockIdx.x * 256 + threadIdx.x;
    g_emb[idx] = __float2half_rn(src[idx]);
}
__global__ __launch_bounds__(256) void wt_f16(const float* __restrict__ src)
{
    const int idx = blockIdx.x * 256 + threadIdx.x;
    g_Wt[idx] = __float2half_rn(src[idx]);
}
__global__ __launch_bounds__(256) void build_wc(
    const float* __restrict__ U_iou, const float* __restrict__ U_f_w)
{
    const int idx = blockIdx.x * 256 + threadIdx.x;
    const int n = idx >> 8, k = idx & 255;
    const float v = (n < 768) ? U_iou[n * 256 + k]
                              : U_f_w[((n - 768) & 255) * 256 + k];
    g_Wc[idx] = __float2half_rn(v);
}

// ---------------------------------------------------------------------------
// Double-buffered single-pass fp16 GEMM (proven config: 256 thr, 2 CTA/SM).
// C[M,N](fp16) = A[M,256] @ B[N,256]^T.  CTA 128x128, K = 4x64, 2-stage.
// MODE 0 (table): A = g_emb,   B = g_Wt,          C = g_table  (6 tiles)
// MODE 1 (level): A = hsum / child h,  B = g_Wc,  C = g_pre    (<=10 tiles)
// MODE 2 (fleaf): A = g_hleaf, B = g_Wc+768 rows, C = g_fpleaf (2 tiles)
// ---------------------------------------------------------------------------
#define SM_A  0u
#define SM_B  16384u
#define STGS  32768u
#define L_SMT 65536

template<int MODE>
__global__ __launch_bounds__(256, 2) void gemm_f16(int base)
{
    extern __shared__ char smem[];
    const uint32_t sb = smem_u32(smem);
    const int tid = threadIdx.x, wid = tid >> 5, lane = tid & 31;
    const int bm = blockIdx.x * 128;
    const int tile = blockIdx.y;
    const int bn = tile * 128;
    const int Nc = (MODE == 0) ? 768 : (MODE == 1) ? NPRE : 256;

    // A source (fp16 plane)
    const __half* a;
    {
        const int r = bm + (tid >> 1);
        if (MODE == 0) {
            a = g_emb + (size_t)r * 256;
        } else if (MODE == 2) {
            a = g_hleaf + (size_t)r * 256;
        } else if (tile < 6) {
            a = g_hsum + (size_t)r * 256;
        } else {
            const int s = (tile - 6) >> 1;
            const int j = r >> 8, bt = r & 255;
            const int child = 2 * (base + j) + 1 + s;
            a = g_h + ((size_t)bt * NTREEN + child) * 256;
        }
        a += (tid & 1) * 32;
    }
    const __half* bbase = (MODE == 0) ? g_Wt
                         : (MODE == 2) ? (g_Wc + (size_t)768 * 256) : g_Wc;
    const __half* b = bbase + (size_t)(bn + (tid >> 1)) * 256 + (tid & 1) * 32;

    const uint32_t rowoff = (uint32_t)(tid >> 1) * 128u;
    const uint32_t rxor   = (uint32_t)(((tid >> 1) & 7) << 4);

    #define LOADC(s, k0) do {                                                  \
        const uint32_t st_ = sb + (uint32_t)(s) * STGS;                        \
        _Pragma("unroll")                                                      \
        for (int j = 0; j < 4; j++) {                                          \
            const uint32_t xo = (uint32_t)((tid & 1) * 64 + j * 16) ^ rxor;    \
            const uint32_t d = rowoff + xo;                                    \
            CP16(st_ + SM_A + d, a + (k0) + j * 8);                            \
            CP16(st_ + SM_B + d, b + (k0) + j * 8);                            \
        }                                                                      \
    } while (0)

    const int wm = (wid & 1) * 64;
    const int wn = (wid >> 1) * 32;
    float acc[4][4][4] = {};

    LOADC(0, 0);
    CP_COMMIT();

    #pragma unroll 1
    for (int kc = 0; kc < 4; kc++) {
        if (kc < 3) {
            LOADC((kc + 1) & 1, (kc + 1) * 64);
            CP_COMMIT();
            CP_WAIT1();
        } else {
            CP_WAIT0();
        }
        __syncthreads();

        const uint32_t st = sb + (uint32_t)(kc & 1) * STGS;
        #pragma unroll
        for (int kg = 0; kg < 4; kg++) {
            uint32_t bf[4][2];
            #pragma unroll
            for (int nf = 0; nf < 4; nf++) {
                const uint32_t nrow = (uint32_t)(wn + nf * 8 + (lane & 7));
                const uint32_t x = (uint32_t)(kg * 32 + ((lane >> 3) & 1) * 16);
                const uint32_t sw = nrow * 128u + (x ^ ((nrow & 7u) << 4));
                ldm_x2(bf[nf], st + SM_B + sw);
            }
            #pragma unroll
            for (int mf = 0; mf < 4; mf++) {
                const uint32_t mrow = (uint32_t)(wm + mf * 16 + (lane & 15));
                const uint32_t x = (uint32_t)(kg * 32 + (lane >> 4) * 16);
                const uint32_t sw = mrow * 128u + (x ^ ((mrow & 7u) << 4));
                uint32_t a4[4];
                ldm_x4(a4, st + SM_A + sw);
                #pragma unroll
                for (int nf = 0; nf < 4; nf++)
                    mma_f16(acc[mf][nf], a4, bf[nf]);
            }
        }
        __syncthreads();
    }
    #undef LOADC

    __half* __restrict__ C = (MODE == 0) ? g_table : (MODE == 1) ? g_pre : g_fpleaf;
    #pragma unroll
    for (int mf = 0; mf < 4; mf++) {
        const int row = bm + wm + mf * 16 + (lane >> 2);
        #pragma unroll
        for (int nf = 0; nf < 4; nf++) {
            const int col = bn + wn + nf * 8 + (lane & 3) * 2;
            *(__half2*)&C[(size_t)row * Nc + col] =
                __floats2half2_rn(acc[mf][nf][0], acc[mf][nf][1]);
            *(__half2*)&C[(size_t)(row + 8) * Nc + col] =
                __floats2half2_rn(acc[mf][nf][2], acc[mf][nf][3]);
        }
    }
}

// ---------------------------------------------------------------------------
// Vocab leaf precompute: per-vocab leaf h (fp16) and c (fp32).
// ---------------------------------------------------------------------------
__global__ __launch_bounds__(256) void vocab_leaf(const float* __restrict__ b_iou)
{
    const int t   = blockIdx.x * 256 + threadIdx.x;
    const int hs4 = t & 63;
    const int v   = t >> 6;

    const float4* bb = (const float4*)b_iou;
    const float4 b0 = bb[hs4], b1 = bb[64 + hs4], b2 = bb[128 + hs4];

    const __half2* t2 = (const __half2*)(g_table + (size_t)v * 768);
    const float4 i4 = ldh4(t2 + hs4 * 2);
    const float4 o4 = ldh4(t2 + 128 + hs4 * 2);
    const float4 u4 = ldh4(t2 + 256 + hs4 * 2);

    float4 cn; float hv[4];
    #define DOLANE(c_, e_)                                       \
    {   float cv = sigf(i4.c_ + b0.c_) * tanhf_(u4.c_ + b2.c_);  \
        cn.c_ = cv;                                              \
        hv[e_] = sigf(o4.c_ + b1.c_) * tanhf_(cv); }
    DOLANE(x, 0) DOLANE(y, 1) DOLANE(z, 2) DOLANE(w, 3)
    #undef DOLANE

    ((float4*)(g_cleaf + (size_t)v * 256))[hs4] = cn;
    ((uint2*)(g_hleaf + (size_t)v * 256))[hs4]  = pack_h4(hv);
}

// ---------------------------------------------------------------------------
// Vocab fc precompute: fc[v] = sig(fpleaf[v] + U_f_b) * c_leaf[v]  (fp16)
// ---------------------------------------------------------------------------
__global__ __launch_bounds__(256) void vocab_fc(const float* __restrict__ U_f_b)
{
    const int t   = blockIdx.x * 256 + threadIdx.x;
    const int hs4 = t & 63;
    const int v   = t >> 6;

    const float4 fb = ((const float4*)U_f_b)[hs4];
    const float4 fp = ldh4((const __half2*)(g_fpleaf + (size_t)v * 256) + hs4 * 2);
    const float4 cl = ((const float4*)(g_cleaf + (size_t)v * 256))[hs4];

    float fc[4];
    fc[0] = sigf(fp.x + fb.x) * cl.x;
    fc[1] = sigf(fp.y + fb.y) * cl.y;
    fc[2] = sigf(fp.z + fb.z) * cl.z;
    fc[3] = sigf(fp.w + fb.w) * cl.w;
    ((uint2*)(g_fc + (size_t)v * 256))[hs4] = pack_h4(fc);
}

// ---------------------------------------------------------------------------
// Leaf hsum: hsum[pair] = hleaf[types[left]] + hleaf[types[right]].
// ---------------------------------------------------------------------------
__global__ __launch_bounds__(256) void leaf_hsum(
    const int* __restrict__ types1, const int* __restrict__ types2)
{
    const int tid = blockIdx.x * 256 + threadIdx.x;
    const int hs4 = tid & 63;
    const int q   = tid >> 6;
    const int bt  = q & 255;
    const int tp  = q >> 8;

    const int* ty = (bt < BATCH) ? types1 + bt * NTREEN
                                 : types2 + (bt - BATCH) * NTREEN;
    const int v0 = ty[511 + 2 * tp];
    const int v1 = ty[511 + 2 * tp + 1];

    const float4 h0 = unp_h4(((const uint2*)(g_hleaf + (size_t)v0 * 256))[hs4]);
    const float4 h1 = unp_h4(((const uint2*)(g_hleaf + (size_t)v1 * 256))[hs4]);

    float hs[4] = { h0.x + h1.x, h0.y + h1.y, h0.z + h1.z, h0.w + h1.w };
    ((uint2*)(g_hsum + (size_t)(tp * 256 + bt) * 256))[hs4] = pack_h4(hs);
}

// ---------------------------------------------------------------------------
// Internal-level elementwise, fused sibling pair + hsum.
// LEAF=1 (level 8): csum = fc[v0] + fc[v1] (precomputed in vocab space).
// LEAF=0: csum from g_pre f-cols + g_c16 children.
// ---------------------------------------------------------------------------
template<int LEAF>
__global__ __launch_bounds__(256) void level_ew_pair(
    const float* __restrict__ b_iou, const float* __restrict__ U_f_b, int cbase,
    const int* __restrict__ types1, const int* __restrict__ types2)
{
    const int tid = blockIdx.x * 256 + threadIdx.x;
    const int hs4 = tid & 63;
    const int q   = tid >> 6;
    const int bt  = q & 255;
    const int tp  = q >> 8;

    const float4* bb = (const float4*)b_iou;
    const float4 b0 = bb[hs4], b1 = bb[64 + hs4], b2 = bb[128 + hs4];
    const float4 fb = ((const float4*)U_f_b)[hs4];

    const int* ty = (bt < BATCH) ? types1 + bt * NTREEN
                                 : types2 + (bt - BATCH) * NTREEN;

    float hsum[4] = {0.f, 0.f, 0.f, 0.f};
    #pragma unroll
    for (int s = 0; s < 2; s++) {
        const int node = cbase + 2 * tp + s;
        const int i    = (2 * tp + s) * 256 + bt;

        const __half2* p2 = (const __half2*)(g_pre + (size_t)i * NPRE);
        const float4 iI = ldh4(p2 + hs4 * 2);
        const float4 iO = ldh4(p2 + 128 + hs4 * 2);
        const float4 iU = ldh4(p2 + 256 + hs4 * 2);

        float4 cs;
        if (LEAF) {
            const int v0 = ty[2 * node + 1];
            const int v1 = ty[2 * node + 2];
            const float4 fc0 = unp_h4(((const uint2*)(g_fc + (size_t)v0 * 256))[hs4]);
            const float4 fc1 = unp_h4(((const uint2*)(g_fc + (size_t)v1 * 256))[hs4]);
            cs = make_float4(fc0.x + fc1.x, fc0.y + fc1.y,
                             fc0.z + fc1.z, fc0.w + fc1.w);
        } else {
            const size_t rc0 = ((size_t)bt * NTREEN + 2 * node + 1) * 256;
            const float4 c0 = unp_h4(((const uint2*)(g_c16 + rc0))[hs4]);
            const float4 c1 = unp_h4(((const uint2*)(g_c16 + rc0 + 256))[hs4]);
            const float4 f0 = ldh4(p2 + 384 + hs4 * 2);
            const float4 f1 = ldh4(p2 + 512 + hs4 * 2);
            cs.x = sigf(f0.x + fb.x) * c0.x + sigf(f1.x + fb.x) * c1.x;
            cs.y = sigf(f0.y + fb.y) * c0.y + sigf(f1.y + fb.y) * c1.y;
            cs.z = sigf(f0.z + fb.z) * c0.z + sigf(f1.z + fb.z) * c1.z;
            cs.w = sigf(f0.w + fb.w) * c0.w + sigf(f1.w + fb.w) * c1.w;
        }

        float cnv[4]; float hv[4];
        #define DOLANE(c_, e_)                                                  \
        {   float cv = sigf(iI.c_ + b0.c_) * tanhf_(iU.c_ + b2.c_) + cs.c_;     \
            cnv[e_] = cv;                                                       \
            hv[e_] = sigf(iO.c_ + b1.c_) * tanhf_(cv);                          \
            hsum[e_] += hv[e_]; }
        DOLANE(x, 0) DOLANE(y, 1) DOLANE(z, 2) DOLANE(w, 3)
        #undef DOLANE

        const size_t rowoff = ((size_t)bt * NTREEN + node) * 256;
        ((uint2*)(g_c16 + rowoff))[hs4] = pack_h4(cnv);
        ((uint2*)(g_h + rowoff))[hs4]   = pack_h4(hv);
    }
    ((uint2*)(g_hsum + (size_t)(tp * 256 + bt) * 256))[hs4] = pack_h4(hsum);
}

// ---------------------------------------------------------------------------
// Root elementwise (node 0, no hsum)
// ---------------------------------------------------------------------------
__global__ __launch_bounds__(256) void level_ew_root(
    const float* __restrict__ b_iou, const float* __restrict__ U_f_b)
{
    const int tid = blockIdx.x * 256 + threadIdx.x;
    const int hs4 = tid & 63;
    const int bt  = tid >> 6;

    const size_t rc0 = ((size_t)bt * NTREEN + 1) * 256;
    const float4 c0 = unp_h4(((const uint2*)(g_c16 + rc0))[hs4]);
    const float4 c1 = unp_h4(((const uint2*)(g_c16 + rc0 + 256))[hs4]);

    const __half2* p2 = (const __half2*)(g_pre + (size_t)bt * NPRE);
    const float4 iI = ldh4(p2 + hs4 * 2);
    const float4 iO = ldh4(p2 + 128 + hs4 * 2);
    const float4 iU = ldh4(p2 + 256 + hs4 * 2);
    const float4 f0 = ldh4(p2 + 384 + hs4 * 2);
    const float4 f1 = ldh4(p2 + 512 + hs4 * 2);

    const float4* bb = (const float4*)b_iou;
    const float4 b0 = bb[hs4], b1 = bb[64 + hs4], b2 = bb[128 + hs4];
    const float4 fb = ((const float4*)U_f_b)[hs4];

    float cnv[4]; float hv[4];
    #define DOLANE(c_, e_)                                                      \
    {   float csum = sigf(f0.c_ + fb.c_) * c0.c_ + sigf(f1.c_ + fb.c_) * c1.c_; \
        float cv = sigf(iI.c_ + b0.c_) * tanhf_(iU.c_ + b2.c_) + csum;          \
        cnv[e_] = cv;                                                           \
        hv[e_] = sigf(iO.c_ + b1.c_) * tanhf_(cv); }
    DOLANE(x, 0) DOLANE(y, 1) DOLANE(z, 2) DOLANE(w, 3)
    #undef DOLANE

    const size_t rowoff = (size_t)bt * NTREEN * 256;
    ((uint2*)(g_c16 + rowoff))[hs4] = pack_h4(cnv);
    ((uint2*)(g_h + rowoff))[hs4]   = pack_h4(hv);
}

// ---------------------------------------------------------------------------
// Final stage 1: 8 partial-sum blocks per batch row.
// ---------------------------------------------------------------------------
__global__ __launch_bounds__(256) void final_part(
    const int* __restrict__ types1, const int* __restrict__ types2)
{
    const int b     = blockIdx.x >> 3;
    const int chunk = blockIdx.x & 7;
    const int hs    = threadIdx.x;

    const int n0 = chunk * 128;
    const int n1 = (chunk == 7) ? NTREEN : n0 + 128;

    const size_t o1 = (size_t)b           * NTREEN * 256 + hs;
    const size_t o2 = (size_t)(b + BATCH) * NTREEN * 256 + hs;
    const int* ty1 = types1 + b * NTREEN;
    const int* ty2 = types2 + b * NTREEN;

    float s1 = 0.f, s2 = 0.f;
    for (int n = n0; n < n1; n++) {
        if (n < 511) {
            s1 += __half2float(g_h[o1 + (size_t)n * 256]);
            s2 += __half2float(g_h[o2 + (size_t)n * 256]);
        } else {
            s1 += __half2float(g_hleaf[(size_t)ty1[n] * 256 + hs]);
            s2 += __half2float(g_hleaf[(size_t)ty2[n] * 256 + hs]);
        }
    }
    g_fpart[(size_t)blockIdx.x * 256 + hs] = make_float2(s1, s2);
}

// ---------------------------------------------------------------------------
// Final stage 2: combine partials, |diff| mean, classifier.
// ---------------------------------------------------------------------------
__global__ __launch_bounds__(256) void final_reduce(
    const float* __restrict__ cls_w, const float* __restrict__ cls_b,
    float* __restrict__ out)
{
    const int b  = blockIdx.x;
    const int hs = threadIdx.x;

    float s1 = 0.f, s2 = 0.f;
    #pragma unroll
    for (int k = 0; k < 8; k++) {
        const float2 p = g_fpart[(size_t)(b * 8 + k) * 256 + hs];
        s1 += p.x; s2 += p.y;
    }
    const float d = fabsf(s1 - s2) * (1.0f / (float)NTREEN);

    float v0 = d * cls_w[hs];
    float v1 = d * cls_w[256 + hs];

    #pragma unroll
    for (int off = 16; off > 0; off >>= 1) {
        v0 += __shfl_down_sync(0xffffffffu, v0, off);
        v1 += __shfl_down_sync(0xffffffffu, v1, off);
    }
    __shared__ float sm0[8], sm1[8];
    const int w = threadIdx.x >> 5, lane = threadIdx.x & 31;
    if (lane == 0) { sm0[w] = v0; sm1[w] = v1; }
    __syncthreads();
    if (threadIdx.x == 0) {
        float t0 = 0.f, t1 = 0.f;
        #pragma unroll
        for (int k = 0; k < 8; k++) { t0 += sm0[k]; t1 += sm1[k]; }
        out[b * 2 + 0] = t0 + cls_b[0];
        out[b * 2 + 1] = t1 + cls_b[1];
    }
}

// ---------------------------------------------------------------------------
// Launch
// ---------------------------------------------------------------------------
extern "C" void kernel_launch(void* const* d_in, const int* in_sizes, int n_in,
                              void* d_out, int out_size)
{
    (void)in_sizes; (void)n_in; (void)out_size;
    const int*   types1 = (const int*)  d_in[0];
    const int*   types2 = (const int*)  d_in[1];
    const float* emb    = (const float*)d_in[2];
    const float* W_iou  = (const float*)d_in[3];
    const float* U_iou  = (const float*)d_in[4];
    const float* b_iou  = (const float*)d_in[5];
    const float* U_f_w  = (const float*)d_in[6];
    const float* U_f_b  = (const float*)d_in[7];
    const float* cls_w  = (const float*)d_in[8];
    const float* cls_b  = (const float*)d_in[9];
    float* out = (float*)d_out;

    cudaFuncSetAttribute(gemm_f16<0>, cudaFuncAttributeMaxDynamicSharedMemorySize, L_SMT);
    cudaFuncSetAttribute(gemm_f16<1>, cudaFuncAttributeMaxDynamicSharedMemorySize, L_SMT);
    cudaFuncSetAttribute(gemm_f16<2>, cudaFuncAttributeMaxDynamicSharedMemorySize, L_SMT);

    // 0) prep: fp16 conversions
    emb_f16<<<VOCABN, 256>>>(emb);
    wt_f16<<<768, 256>>>(W_iou);
    build_wc<<<NPRE, 256>>>(U_iou, U_f_w);

    // 1) vocab table + per-vocab leaf h/c, then per-vocab f-pre and fc
    gemm_f16<0><<<dim3(VOCABN / 128, 6), 256, L_SMT>>>(0);
    vocab_leaf<<<VOCABN / 4, 256>>>(b_iou);
    gemm_f16<2><<<dim3(VOCABN / 128, 2), 256, L_SMT>>>(0);
    vocab_fc<<<VOCABN / 4, 256>>>(U_f_b);

    // 2) leaf hsum
    leaf_hsum<<<16384, 256>>>(types1, types2);

    // 3) level 8: iou GEMM only (6 tiles), f-part comes from vocab fc
    {
        const int base = 255;
        gemm_f16<1><<<dim3((BTN << 8) / 128, 6), 256, L_SMT>>>(base);
        level_ew_pair<1><<<64 << 7, 256>>>(b_iou, U_f_b, base, types1, types2);
    }

    // 4) internal levels 7..1 (full 10-tile GEMM)
    for (int lvl = 7; lvl >= 1; --lvl) {
        const int base = (1 << lvl) - 1;
        gemm_f16<1><<<dim3((BTN << lvl) / 128, 10), 256, L_SMT>>>(base);
        level_ew_pair<0><<<64 << (lvl - 1), 256>>>(b_iou, U_f_b, base, types1, types2);
    }

    // 5) root level
    gemm_f16<1><<<dim3(2, 10), 256, L_SMT>>>(0);
    level_ew_root<<<64, 256>>>(b_iou, U_f_b);

    // 6) classifier
    final_part<<<BATCH * 8, 256>>>(types1, types2);
    final_reduce<<<BATCH, 256>>>(cls_w, cls_b, out);
}